// round 10
// baseline (speedup 1.0000x reference)
#include <cuda_runtime.h>
#include <cuda_fp16.h>
#include <cstdint>

#define HW_ 256
#define C_  32
#define O_  32
#define B_  8
#define APX 20                        // A words per pixel (16 fp16x2 + 4 pad)

// smem word offsets
#define SM_BIAS 0
#define SM_DWS  32
#define SM_GS   (SM_DWS + 288)        // 320  (2 rows x 256)
#define SM_A    (SM_GS + 512)         // 832
#define SM_B    (SM_A + 4*258*APX)    // 832 + 20640 = 21472
#define SM_TOT_W (SM_B + 9*2*384)     // 28384
#define SM_TOT_BYTES (SM_TOT_W * 4)   // 113536 bytes

#define STG_STRIDE 36                 // staging o-stride (words), conflict-free

__device__ __forceinline__ uint32_t smem_u32(const void* p) {
    uint32_t a;
    asm("{ .reg .u64 t; cvta.to.shared.u64 t, %1; cvt.u32.u64 %0, t; }" : "=r"(a) : "l"(p));
    return a;
}

__device__ __forceinline__ uint32_t pk2h(float a, float b) {
    __half2 h = __floats2half2_rn(a, b);
    return *reinterpret_cast<uint32_t*>(&h);
}

__device__ __forceinline__ void ldsm4(uint32_t& r0, uint32_t& r1, uint32_t& r2, uint32_t& r3,
                                      uint32_t addr) {
    asm volatile("ldmatrix.sync.aligned.m8n8.x4.shared.b16 {%0,%1,%2,%3}, [%4];"
                 : "=r"(r0), "=r"(r1), "=r"(r2), "=r"(r3) : "r"(addr));
}

__device__ __forceinline__ void mma16816(float* c, uint32_t a0, uint32_t a1,
                                         uint32_t a2, uint32_t a3,
                                         uint32_t b0, uint32_t b1) {
    asm volatile(
        "mma.sync.aligned.m16n8k16.row.col.f32.f16.f16.f32 "
        "{%0,%1,%2,%3}, {%4,%5,%6,%7}, {%8,%9}, {%0,%1,%2,%3};"
        : "+f"(c[0]), "+f"(c[1]), "+f"(c[2]), "+f"(c[3])
        : "r"(a0), "r"(a1), "r"(a2), "r"(a3), "r"(b0), "r"(b1));
}

__global__ __launch_bounds__(512, 1)
void dynamiconv_kernel(const float* __restrict__ x, const float* __restrict__ weight,
                       const float* __restrict__ dweight, const float* __restrict__ bias,
                       float* __restrict__ out)
{
    extern __shared__ char smraw[];
    uint32_t* smw    = (uint32_t*)smraw;
    float*    smf    = (float*)smraw;
    float*    bias_s = smf;                      // SM_BIAS
    float*    dws_s  = smf + SM_DWS;
    float*    gs     = smf + SM_GS;              // [row 0..1][px 0..255]

    const int tid  = threadIdx.x;
    const int lane = tid & 31;
    const int warp = tid >> 5;                   // 0..15
    const int y0 = blockIdx.x * 2;               // 2 output rows per CTA
    const int b  = blockIdx.y;

    if (tid < 32) bias_s[tid] = bias[tid];
    if (tid < 288) dws_s[tid] = dweight[tid];

    // ---- B fill (threads 0..255): thread owns contiguous 36-float weight chunk ----
    if (tid < 256) {
        float wchunk[36];
        const float4* ws4 = (const float4*)(weight + tid * 36);
        #pragma unroll
        for (int j = 0; j < 9; j++) ((float4*)wchunk)[j] = ws4[j];
        const int o    = tid >> 3;
        const int kpg0 = (tid & 7) * 2;
        const int kch0 = kpg0 >> 3, kp0 = kpg0 & 7;
        const int kpg1 = kpg0 + 1;
        const int kch1 = kpg1 >> 3, kp1 = kpg1 & 7;
        #pragma unroll
        for (int tap = 0; tap < 9; tap++) {
            smw[SM_B + (tap*2 + kch0)*384 + o*12 + kp0] = pk2h(wchunk[tap],      wchunk[tap + 9]);
            smw[SM_B + (tap*2 + kch1)*384 + o*12 + kp1] = pk2h(wchunk[tap + 18], wchunk[tap + 27]);
        }
    }

    // ---- A fill: 4 halo rows (y0-1 .. y0+2); thread = (rowpair, pixel) ----
    const float* xb = x + (size_t)b * C_ * HW_ * HW_;
    {
        const int h  = tid >> 8;            // 0: halo rows 0,1   1: halo rows 2,3
        const int gx = tid & 255;
        #pragma unroll
        for (int rr = 0; rr < 2; rr++) {
            int r  = h * 2 + rr;
            int gy = y0 - 1 + r;
            bool inb = ((unsigned)gy < (unsigned)HW_);
            const float* src = xb + (size_t)gy * HW_ + gx;
            uint32_t* dst = smw + SM_A + (r * 258 + gx + 1) * APX;
            #pragma unroll
            for (int q = 0; q < 4; q++) {
                float v[8];
                #pragma unroll
                for (int j = 0; j < 8; j++)
                    v[j] = inb ? src[(size_t)(8*q + j) * (HW_*HW_)] : 0.f;
                uint4 w = make_uint4(pk2h(v[0], v[1]), pk2h(v[2], v[3]),
                                     pk2h(v[4], v[5]), pk2h(v[6], v[7]));
                *(uint4*)(dst + 4*q) = w;
            }
        }
        // halo edge columns hp=0 and hp=257 -> zero (32 STS.128)
        if (tid < 32) {
            int r = tid >> 3, rem = tid & 7, e = rem >> 2, q = rem & 3;
            *(uint4*)(smw + SM_A + (r * 258 + e * 257) * APX + 4*q) = make_uint4(0,0,0,0);
        }
    }
    __syncthreads();

    const int row = warp >> 3;            // output row within CTA (0/1)
    const int pxw = (warp & 7) * 32;      // pixel strip

    // ================= gate pass (lane = channel; transpose-reduce) =================
    {
        const int c = lane;
        const int sh = (lane & 1) * 16;
        float dwr[9], sd2 = 0.f;
        #pragma unroll
        for (int j = 0; j < 9; j++) { dwr[j] = 0.5f * dws_s[c * 9 + j]; sd2 += dwr[j]; }
        const int arow = row * 258;       // halo rows row..row+2

        float c0[3], c1[3];
        #pragma unroll
        for (int r = 0; r < 3; r++) {
            uint32_t w0 = smw[SM_A + ((arow + r * 258) + pxw)     * APX + (c >> 1)];
            uint32_t w1 = smw[SM_A + ((arow + r * 258) + pxw + 1) * APX + (c >> 1)];
            float v0 = __half2float(__ushort_as_half((unsigned short)(w0 >> sh)));
            float v1 = __half2float(__ushort_as_half((unsigned short)(w1 >> sh)));
            asm("tanh.approx.f32 %0, %1;" : "=f"(c0[r]) : "f"(v0 * 0.5f));
            asm("tanh.approx.f32 %0, %1;" : "=f"(c1[r]) : "f"(v1 * 0.5f));
        }
        float v[16];
        #pragma unroll
        for (int px = 0; px < 32; px++) {
            float c2[3];
            #pragma unroll
            for (int r = 0; r < 3; r++) {
                uint32_t w = smw[SM_A + ((arow + r * 258) + pxw + px + 2) * APX + (c >> 1)];
                float vv = __half2float(__ushort_as_half((unsigned short)(w >> sh)));
                asm("tanh.approx.f32 %0, %1;" : "=f"(c2[r]) : "f"(vv * 0.5f));
            }
            float p = sd2;
            #pragma unroll
            for (int r = 0; r < 3; r++) {
                p = fmaf(dwr[r * 3 + 0], c0[r], p);
                p = fmaf(dwr[r * 3 + 1], c1[r], p);
                p = fmaf(dwr[r * 3 + 2], c2[r], p);
            }
            v[px & 15] = p;
            #pragma unroll
            for (int r = 0; r < 3; r++) { c0[r] = c1[r]; c1[r] = c2[r]; }

            if ((px & 15) == 15) {
                #pragma unroll
                for (int i = 0; i < 16; i++)
                    v[i] += __shfl_xor_sync(0xFFFFFFFFu, v[i], 16);
                #pragma unroll
                for (int i = 0; i < 8; i++) {
                    float snd = (lane & 8) ? v[i] : v[i+8];
                    float kpv = (lane & 8) ? v[i+8] : v[i];
                    v[i] = kpv + __shfl_xor_sync(0xFFFFFFFFu, snd, 8);
                }
                #pragma unroll
                for (int i = 0; i < 4; i++) {
                    float snd = (lane & 4) ? v[i] : v[i+4];
                    float kpv = (lane & 4) ? v[i+4] : v[i];
                    v[i] = kpv + __shfl_xor_sync(0xFFFFFFFFu, snd, 4);
                }
                #pragma unroll
                for (int i = 0; i < 2; i++) {
                    float snd = (lane & 2) ? v[i] : v[i+2];
                    float kpv = (lane & 2) ? v[i+2] : v[i];
                    v[i] = kpv + __shfl_xor_sync(0xFFFFFFFFu, snd, 2);
                }
                {
                    float snd = (lane & 1) ? v[0] : v[1];
                    float kpv = (lane & 1) ? v[1] : v[0];
                    v[0] = kpv + __shfl_xor_sync(0xFFFFFFFFu, snd, 1);
                }
                if (lane < 16) gs[row * 256 + pxw + (px & ~15) + lane] = v[0];
            }
        }
    }
    __syncthreads();

    // ================= mainloop: ldmatrix + mma (fp16) =================
    const uint32_t sbase = smem_u32(smraw);
    const uint32_t Abase = sbase + SM_A * 4;
    const uint32_t Bbase = sbase + SM_B * 4;
    const uint32_t laneA = ((((lane >> 3) & 1) * 8 + (lane & 7)) * APX + (lane >> 4) * 4) * 4;
    const uint32_t laneB = ((((lane >> 4) & 1) * 8 + (lane & 7)) * 12 + ((lane >> 3) & 1) * 4) * 4;

    float acc[2][4][4];
    #pragma unroll
    for (int mb = 0; mb < 2; mb++)
        #pragma unroll
        for (int nb = 0; nb < 4; nb++)
            #pragma unroll
            for (int r = 0; r < 4; r++) acc[mb][nb][r] = 0.0f;

    #pragma unroll 1
    for (int ki = 0; ki < 3; ki++) {
        #pragma unroll 1
        for (int kj = 0; kj < 3; kj++) {
            uint32_t aaddr = Abase + (uint32_t)(((row + ki) * 258 + pxw + kj) * APX * 4) + laneA;
            uint32_t baddr = Bbase + (uint32_t)((ki * 3 + kj) * 3072) + laneB;
            uint32_t a0[8], a1[8], b0q[8], b1q[8];
            ldsm4(a0[0], a0[1], a0[2], a0[3], aaddr);
            ldsm4(a0[4], a0[5], a0[6], a0[7], aaddr + 16 * APX * 4);
            ldsm4(b0q[0], b0q[1], b0q[2], b0q[3], baddr);
            ldsm4(b0q[4], b0q[5], b0q[6], b0q[7], baddr + 768);
            ldsm4(a1[0], a1[1], a1[2], a1[3], aaddr + 32);
            ldsm4(a1[4], a1[5], a1[6], a1[7], aaddr + 16 * APX * 4 + 32);
            ldsm4(b1q[0], b1q[1], b1q[2], b1q[3], baddr + 1536);
            ldsm4(b1q[4], b1q[5], b1q[6], b1q[7], baddr + 1536 + 768);
            #pragma unroll
            for (int mb = 0; mb < 2; mb++) {
                #pragma unroll
                for (int nb = 0; nb < 4; nb++)
                    mma16816(acc[mb][nb], a0[mb*4+0], a0[mb*4+1], a0[mb*4+2], a0[mb*4+3],
                             b0q[2*nb], b0q[2*nb+1]);
                #pragma unroll
                for (int nb = 0; nb < 4; nb++)
                    mma16816(acc[mb][nb], a1[mb*4+0], a1[mb*4+1], a1[mb*4+2], a1[mb*4+3],
                             b1q[2*nb], b1q[2*nb+1]);
            }
        }
    }

    // ================= epilogue: gate*acc + bias, smem transpose, STG.128 =================
    const int tig = lane & 3, grp = lane >> 2;
    __syncthreads();     // all warps done reading A before staging overwrites it

    float* st = smf + SM_A + warp * (32 * STG_STRIDE);   // per-warp 32o x 36w staging
    #pragma unroll
    for (int mb = 0; mb < 2; mb++) {
        int pxl = mb * 16 + grp;
        float g0 = gs[row * 256 + pxw + pxl], g1 = gs[row * 256 + pxw + pxl + 8];
        #pragma unroll
        for (int nb = 0; nb < 4; nb++) {
            int o = nb * 8 + tig * 2;
            float bi0 = bias_s[o], bi1 = bias_s[o + 1];
            st[o       * STG_STRIDE + pxl]     = fmaf(g0, acc[mb][nb][0], bi0);
            st[(o + 1) * STG_STRIDE + pxl]     = fmaf(g0, acc[mb][nb][1], bi1);
            st[o       * STG_STRIDE + pxl + 8] = fmaf(g1, acc[mb][nb][2], bi0);
            st[(o + 1) * STG_STRIDE + pxl + 8] = fmaf(g1, acc[mb][nb][3], bi1);
        }
    }
    __syncwarp();

    {
        const int g = lane >> 3, i = lane & 7;
        float* ob = out + (size_t)b * O_ * HW_ * HW_ + (size_t)(y0 + row) * HW_ + pxw;
        #pragma unroll
        for (int it = 0; it < 8; it++) {
            int o = it * 4 + g;
            float4 v = *(const float4*)(st + o * STG_STRIDE + i * 4);
            *(float4*)(ob + (size_t)o * (HW_*HW_) + i * 4) = v;
        }
    }
}

extern "C" void kernel_launch(void* const* d_in, const int* in_sizes, int n_in,
                              void* d_out, int out_size)
{
    const float* x       = (const float*)d_in[0];
    const float* weight  = (const float*)d_in[1];
    const float* dweight = (const float*)d_in[2];
    const float* bias    = (const float*)d_in[3];
    float* out = (float*)d_out;

    cudaFuncSetAttribute(dynamiconv_kernel,
                         cudaFuncAttributeMaxDynamicSharedMemorySize, SM_TOT_BYTES);

    dim3 grid(HW_ / 2, B_, 1);   // 128 row-pairs x 8 batches = 1024 CTAs
    dynamiconv_kernel<<<grid, 512, SM_TOT_BYTES>>>(x, weight, dweight, bias, out);
}